// round 2
// baseline (speedup 1.0000x reference)
#include <cuda_runtime.h>

// Problem constants (fixed shapes for this problem)
#define Nn    50000
#define FIN   128
#define D1    128           // H1*C1
#define H1    2
#define NC    16
#define EMAX  1600000
#define ETMAX (EMAX + Nn)

// ---------------- scratch (device globals; no allocation allowed) ------------
__device__ float4  g_w1t4[(FIN / 4) * D1];  // [k4][o] -> w1 values for k=4k4..4k4+3
__device__ float4  g_w2t4[(D1 / 4) * NC];
__device__ float   g_xw1[Nn * D1];
__device__ float   g_out1[Nn * D1];
__device__ float   g_asrc1[Nn * H1];
__device__ float   g_adst1[Nn * H1];
__device__ unsigned g_m1[Nn * H1];
__device__ float   g_s1[Nn * H1];
__device__ float   g_e1[ETMAX * H1];
__device__ float   g_xw2[Nn * NC];
__device__ float   g_asrc2[Nn];
__device__ float   g_adst2[Nn];
__device__ unsigned g_m2[Nn];
__device__ float   g_s2[Nn];
__device__ float   g_e2[ETMAX];

// monotonic float <-> unsigned encoding for atomicMax on floats
__device__ __forceinline__ unsigned fenc(float f) {
    unsigned b = __float_as_uint(f);
    return (b & 0x80000000u) ? ~b : (b | 0x80000000u);
}
__device__ __forceinline__ float fdec(unsigned u) {
    return __uint_as_float((u & 0x80000000u) ? (u ^ 0x80000000u) : ~u);
}
__device__ __forceinline__ float lrelu(float a) { return a > 0.f ? a : 0.2f * a; }

// ---------------- weight transpose / repack ---------------------------------
__global__ void k_prep(const float* __restrict__ w1, const float* __restrict__ w2) {
    int i = blockIdx.x * blockDim.x + threadIdx.x;
    if (i < FIN * D1) {
        int o = i / FIN, k = i % FIN;             // w1: [D1][FIN] row-major
        ((float*)g_w1t4)[((k >> 2) * D1 + o) * 4 + (k & 3)] = w1[i];
    }
    int j = i - FIN * D1;
    if (j >= 0 && j < NC * D1) {
        int o = j / D1, k = j % D1;               // w2: [NC][D1]
        ((float*)g_w2t4)[((k >> 2) * NC + o) * 4 + (k & 3)] = w2[j];
    }
}

// ---------------- layer-1 GEMM: xw1 = x @ w1^T -------------------------------
__global__ void k_gemm1(const float* __restrict__ x, int n) {
    __shared__ float xs[8][FIN];
    int t  = threadIdx.x;          // 0..127 = output channel
    int nb = blockIdx.x * 8;
#pragma unroll
    for (int i = 0; i < 8; i++) {
        int node = nb + i;
        xs[i][t] = (node < n) ? x[node * FIN + t] : 0.f;
    }
    __syncthreads();
    float acc[8] = {0.f, 0.f, 0.f, 0.f, 0.f, 0.f, 0.f, 0.f};
#pragma unroll
    for (int k4 = 0; k4 < FIN / 4; k4++) {
        float4 w = g_w1t4[k4 * D1 + t];
#pragma unroll
        for (int i = 0; i < 8; i++) {
            float4 xv = *(const float4*)&xs[i][k4 * 4];
            acc[i] += xv.x * w.x + xv.y * w.y + xv.z * w.z + xv.w * w.w;
        }
    }
#pragma unroll
    for (int i = 0; i < 8; i++) {
        int node = nb + i;
        if (node < n) g_xw1[node * D1 + t] = acc[i];
    }
}

// ---------------- layer-1 attention dots: a_src/a_dst per node ---------------
__global__ void k_att1(const float* __restrict__ att_s, const float* __restrict__ att_d, int n) {
    int gt   = blockIdx.x * blockDim.x + threadIdx.x;
    int node = gt >> 5;
    if (node >= n) return;
    int lane = gt & 31;
    float4 v  = *(const float4*)&g_xw1[node * D1 + lane * 4];
    float4 a1 = *(const float4*)&att_s[lane * 4];
    float4 a2 = *(const float4*)&att_d[lane * 4];
    float ps = v.x * a1.x + v.y * a1.y + v.z * a1.z + v.w * a1.w;
    float pd = v.x * a2.x + v.y * a2.y + v.z * a2.z + v.w * a2.w;
#pragma unroll
    for (int o = 8; o >= 1; o >>= 1) {       // reduce within 16-lane halves (= heads)
        ps += __shfl_xor_sync(0xffffffffu, ps, o);
        pd += __shfl_xor_sync(0xffffffffu, pd, o);
    }
    if ((lane & 15) == 0) {
        int h = lane >> 4;
        g_asrc1[node * 2 + h] = ps;
        g_adst1[node * 2 + h] = pd;
    }
}

__global__ void k_init1(const float* __restrict__ b1, int n) {
    int i = blockIdx.x * blockDim.x + threadIdx.x;
    if (i < n * D1) g_out1[i] = b1[i & (D1 - 1)];
    if (i < n * H1) { g_m1[i] = 0u; g_s1[i] = 0.f; }
}

// ---------------- layer-1 edge passes ----------------------------------------
__global__ void k_emax1(const int* __restrict__ ei, int E, int ET) {
    int e = blockIdx.x * blockDim.x + threadIdx.x;
    if (e >= ET) return;
    int s, d;
    if (e < E) { s = ei[e]; d = ei[E + e]; } else { s = d = e - E; }
    float2 as = *(const float2*)&g_asrc1[s * 2];
    float2 ad = *(const float2*)&g_adst1[d * 2];
    float a0 = lrelu(as.x + ad.x);
    float a1 = lrelu(as.y + ad.y);
    atomicMax(&g_m1[d * 2 + 0], fenc(a0));
    atomicMax(&g_m1[d * 2 + 1], fenc(a1));
}

__global__ void k_esum1(const int* __restrict__ ei, int E, int ET) {
    int e = blockIdx.x * blockDim.x + threadIdx.x;
    if (e >= ET) return;
    int s, d;
    if (e < E) { s = ei[e]; d = ei[E + e]; } else { s = d = e - E; }
    float2 as = *(const float2*)&g_asrc1[s * 2];
    float2 ad = *(const float2*)&g_adst1[d * 2];
    float a0 = lrelu(as.x + ad.x);
    float a1 = lrelu(as.y + ad.y);
    float m0 = fdec(g_m1[d * 2 + 0]);
    float m1 = fdec(g_m1[d * 2 + 1]);
    float e0 = __expf(a0 - m0);
    float e1 = __expf(a1 - m1);
    g_e1[e * 2 + 0] = e0;
    g_e1[e * 2 + 1] = e1;
    atomicAdd(&g_s1[d * 2 + 0], e0);
    atomicAdd(&g_s1[d * 2 + 1], e1);
}

// one warp per edge: coalesced 512B gather + 4 atomics/lane to consecutive addrs
__global__ void k_eagg1(const int* __restrict__ ei, int E, int ET) {
    int gt = blockIdx.x * blockDim.x + threadIdx.x;
    int e  = gt >> 5;
    if (e >= ET) return;
    int lane = gt & 31;
    int s, d;
    if (e < E) { s = ei[e]; d = ei[E + e]; } else { s = d = e - E; }
    int h = lane >> 4;
    float coef = g_e1[e * 2 + h] / (g_s1[d * 2 + h] + 1e-16f);
    float4 v = *(const float4*)&g_xw1[s * D1 + lane * 4];
    float* o = &g_out1[d * D1 + lane * 4];
    atomicAdd(o + 0, v.x * coef);
    atomicAdd(o + 1, v.y * coef);
    atomicAdd(o + 2, v.z * coef);
    atomicAdd(o + 3, v.w * coef);
}

// ---------------- layer-2 GEMM (relu fused on load) + att2 dots --------------
__global__ void k_gemm2(const float* __restrict__ att_s, const float* __restrict__ att_d, int n) {
    __shared__ float xs[8 * 132];    // padded rows: conflict-free LDS.128
    int t  = threadIdx.x;            // 128 threads = 8 nodes x 16 outs
    int nb = blockIdx.x * 8;
#pragma unroll
    for (int i = 0; i < 8; i++) {
        int node = nb + i;
        float v = (node < n) ? g_out1[node * D1 + t] : 0.f;
        xs[i * 132 + t] = fmaxf(v, 0.f);     // relu
    }
    __syncthreads();
    int ni = t >> 4;
    int o  = t & 15;
    float a0 = 0.f, a1 = 0.f, a2 = 0.f, a3 = 0.f;
#pragma unroll
    for (int k4 = 0; k4 < D1 / 4; k4 += 4) {
#pragma unroll
        for (int u = 0; u < 4; u++) {
            float4 w  = g_w2t4[(k4 + u) * NC + o];
            float4 xv = *(const float4*)&xs[ni * 132 + (k4 + u) * 4];
            float p = xv.x * w.x + xv.y * w.y + xv.z * w.z + xv.w * w.w;
            if (u == 0) a0 += p; else if (u == 1) a1 += p; else if (u == 2) a2 += p; else a3 += p;
        }
    }
    float acc = (a0 + a1) + (a2 + a3);
    int node = nb + ni;
    if (node < n) g_xw2[node * NC + o] = acc;
    float ps = acc * att_s[o];
    float pd = acc * att_d[o];
#pragma unroll
    for (int j = 8; j >= 1; j >>= 1) {
        ps += __shfl_xor_sync(0xffffffffu, ps, j);
        pd += __shfl_xor_sync(0xffffffffu, pd, j);
    }
    if (o == 0 && node < n) { g_asrc2[node] = ps; g_adst2[node] = pd; }
}

__global__ void k_init2(const float* __restrict__ b2, float* __restrict__ out, int n) {
    int i = blockIdx.x * blockDim.x + threadIdx.x;
    if (i < n * NC) out[i] = b2[i & (NC - 1)];
    if (i < n) { g_m2[i] = 0u; g_s2[i] = 0.f; }
}

__global__ void k_emax2(const int* __restrict__ ei, int E, int ET) {
    int e = blockIdx.x * blockDim.x + threadIdx.x;
    if (e >= ET) return;
    int s, d;
    if (e < E) { s = ei[e]; d = ei[E + e]; } else { s = d = e - E; }
    float a = lrelu(g_asrc2[s] + g_adst2[d]);
    atomicMax(&g_m2[d], fenc(a));
}

__global__ void k_esum2(const int* __restrict__ ei, int E, int ET) {
    int e = blockIdx.x * blockDim.x + threadIdx.x;
    if (e >= ET) return;
    int s, d;
    if (e < E) { s = ei[e]; d = ei[E + e]; } else { s = d = e - E; }
    float a  = lrelu(g_asrc2[s] + g_adst2[d]);
    float ev = __expf(a - fdec(g_m2[d]));
    g_e2[e] = ev;
    atomicAdd(&g_s2[d], ev);
}

__global__ void k_eagg2(const int* __restrict__ ei, float* __restrict__ out, int E, int ET) {
    long long gt = (long long)blockIdx.x * blockDim.x + threadIdx.x;
    if (gt >= (long long)ET * NC) return;
    int e = (int)(gt >> 4);
    int c = (int)(gt & 15);
    int s, d;
    if (e < E) { s = ei[e]; d = ei[E + e]; } else { s = d = e - E; }
    float coef = g_e2[e] / (g_s2[d] + 1e-16f);
    atomicAdd(&out[d * NC + c], g_xw2[s * NC + c] * coef);
}

// ---------------- launcher ----------------------------------------------------
extern "C" void kernel_launch(void* const* d_in, const int* in_sizes, int n_in,
                              void* d_out, int out_size) {
    const float* x   = (const float*)d_in[0];
    const int*   ei  = (const int*)d_in[1];      // int32 (jax default, no x64)
    const float* w1  = (const float*)d_in[2];
    const float* as1 = (const float*)d_in[3];
    const float* ad1 = (const float*)d_in[4];
    const float* b1  = (const float*)d_in[5];
    const float* w2  = (const float*)d_in[6];
    const float* as2 = (const float*)d_in[7];
    const float* ad2 = (const float*)d_in[8];
    const float* b2  = (const float*)d_in[9];
    float* out = (float*)d_out;

    int n  = in_sizes[0] / FIN;     // 50000
    int E  = in_sizes[1] / 2;       // 1600000
    int ET = E + n;                 // 1650000

    k_prep<<<(FIN * D1 + NC * D1 + 255) / 256, 256>>>(w1, w2);

    // layer 1
    k_gemm1<<<(n + 7) / 8, 128>>>(x, n);
    k_att1<<<(n * 32 + 255) / 256, 256>>>(as1, ad1, n);
    k_init1<<<(n * D1 + 255) / 256, 256>>>(b1, n);
    k_emax1<<<(ET + 255) / 256, 256>>>(ei, E, ET);
    k_esum1<<<(ET + 255) / 256, 256>>>(ei, E, ET);
    {
        long long tot = (long long)ET * 32;
        k_eagg1<<<(int)((tot + 255) / 256), 256>>>(ei, E, ET);
    }

    // layer 2 (relu fused into gemm2 load; att2 fused into gemm2 epilogue)
    k_gemm2<<<(n + 7) / 8, 128>>>(as2, ad2, n);
    k_init2<<<(n * NC + 255) / 256, 256>>>(b2, out, n);
    k_emax2<<<(ET + 255) / 256, 256>>>(ei, E, ET);
    k_esum2<<<(ET + 255) / 256, 256>>>(ei, E, ET);
    {
        long long tot = (long long)ET * NC;
        k_eagg2<<<(int)((tot + 255) / 256), 256>>>(ei, out, E, ET);
    }
}

// round 3
// speedup vs baseline: 2.3851x; 2.3851x over previous
#include <cuda_runtime.h>

// Problem constants (fixed shapes for this problem)
#define Nn    50000
#define FIN   128
#define D1    128           // H1*C1
#define H1    2
#define NC    16
#define EMAX  1600000
#define ETMAX (EMAX + Nn)

// ---------------- scratch (device globals; no allocation allowed) ------------
__device__ float4   g_w1t[128 * 32];        // [k][c4] -> w1[c4*4+cc][k]
__device__ float4   g_w2t4[(D1 / 4) * NC];  // [k4][o]
__device__ float    g_xw1[Nn * D1];
__device__ float    g_out1[Nn * D1];
__device__ float    g_asrc1[Nn * H1];
__device__ float    g_adst1[Nn * H1];
__device__ float    g_xw2[Nn * NC];
__device__ float    g_asrc2[Nn];
__device__ float    g_adst2[Nn];
__device__ unsigned g_cnt[Nn];
__device__ unsigned g_off[Nn + 1];
__device__ unsigned g_cur[Nn];
__device__ int      g_adj[ETMAX];           // CSR by dst: src node ids

__device__ __forceinline__ float lrelu(float a) { return a > 0.f ? a : 0.2f * a; }

// ---------------- weight repack + counter zero -------------------------------
__global__ void k_prep(const float* __restrict__ w1, const float* __restrict__ w2, int n) {
    int i = blockIdx.x * blockDim.x + threadIdx.x;
    if (i < FIN * D1) {
        int c = i / FIN, k = i % FIN;             // w1: [D1][FIN] row-major
        ((float*)g_w1t)[(k * 32 + (c >> 2)) * 4 + (c & 3)] = w1[i];
    }
    if (i < NC * D1) {
        int o = i / D1, k = i % D1;               // w2: [NC][D1]
        ((float*)g_w2t4)[((k >> 2) * NC + o) * 4 + (k & 3)] = w2[i];
    }
    if (i < n) g_cnt[i] = 0u;
}

// ---------------- CSR build ---------------------------------------------------
__global__ void k_hist(const int* __restrict__ ei, int E, int ET) {
    int e = blockIdx.x * blockDim.x + threadIdx.x;
    if (e >= ET) return;
    int d = (e < E) ? ei[E + e] : (e - E);
    atomicAdd(&g_cnt[d], 1u);
}

__global__ void k_scan(int n) {
    __shared__ unsigned ssum[1024];
    int t = threadIdx.x;
    int chunk = (n + 1023) >> 10;
    int b = t * chunk;
    int e = min(b + chunk, n);
    unsigned sum = 0;
    for (int i = b; i < e; i++) sum += g_cnt[i];
    ssum[t] = sum;
    __syncthreads();
    for (int o = 1; o < 1024; o <<= 1) {
        unsigned v = (t >= o) ? ssum[t - o] : 0u;
        __syncthreads();
        ssum[t] += v;
        __syncthreads();
    }
    unsigned run = (t == 0) ? 0u : ssum[t - 1];
    for (int i = b; i < e; i++) {
        unsigned c = g_cnt[i];
        g_off[i] = run;
        g_cur[i] = run;
        run += c;
    }
    if (t == 0) g_off[n] = ssum[1023];
}

__global__ void k_scatter(const int* __restrict__ ei, int E, int ET) {
    int e = blockIdx.x * blockDim.x + threadIdx.x;
    if (e >= ET) return;
    int s, d;
    if (e < E) { s = ei[e]; d = ei[E + e]; } else { s = d = e - E; }
    unsigned pos = atomicAdd(&g_cur[d], 1u);
    g_adj[pos] = s;
}

// ---------------- layer-1 GEMM: xw1 = x @ w1^T (32 nodes/block) --------------
__global__ __launch_bounds__(256) void k_gemm1(const float* __restrict__ x, int n) {
    __shared__ float xs[128 * 33];
    int tid = threadIdx.x;
    int nb  = blockIdx.x * 32;
    for (int idx = tid; idx < 32 * 128; idx += 256) {
        int node = idx >> 7, k = idx & 127;
        xs[k * 33 + node] = (nb + node < n) ? x[(nb + node) * FIN + k] : 0.f;
    }
    __syncthreads();
    int c4 = tid & 31;     // channels c4*4 .. c4*4+3
    int ng = tid >> 5;     // nodes ng*4 .. ng*4+3
    float acc[4][4];
#pragma unroll
    for (int i = 0; i < 4; i++)
#pragma unroll
        for (int j = 0; j < 4; j++) acc[i][j] = 0.f;
#pragma unroll 8
    for (int k = 0; k < 128; k++) {
        float4 w = g_w1t[k * 32 + c4];
        float xv0 = xs[k * 33 + ng * 4 + 0];
        float xv1 = xs[k * 33 + ng * 4 + 1];
        float xv2 = xs[k * 33 + ng * 4 + 2];
        float xv3 = xs[k * 33 + ng * 4 + 3];
        acc[0][0] += xv0 * w.x; acc[0][1] += xv0 * w.y; acc[0][2] += xv0 * w.z; acc[0][3] += xv0 * w.w;
        acc[1][0] += xv1 * w.x; acc[1][1] += xv1 * w.y; acc[1][2] += xv1 * w.z; acc[1][3] += xv1 * w.w;
        acc[2][0] += xv2 * w.x; acc[2][1] += xv2 * w.y; acc[2][2] += xv2 * w.z; acc[2][3] += xv2 * w.w;
        acc[3][0] += xv3 * w.x; acc[3][1] += xv3 * w.y; acc[3][2] += xv3 * w.z; acc[3][3] += xv3 * w.w;
    }
#pragma unroll
    for (int i = 0; i < 4; i++) {
        int node = nb + ng * 4 + i;
        if (node < n)
            *(float4*)&g_xw1[node * D1 + c4 * 4] =
                make_float4(acc[i][0], acc[i][1], acc[i][2], acc[i][3]);
    }
}

// ---------------- layer-1 attention dots -------------------------------------
__global__ void k_att1(const float* __restrict__ att_s, const float* __restrict__ att_d, int n) {
    int gt   = blockIdx.x * blockDim.x + threadIdx.x;
    int node = gt >> 5;
    if (node >= n) return;
    int lane = gt & 31;
    float4 v  = *(const float4*)&g_xw1[node * D1 + lane * 4];
    float4 a1 = *(const float4*)&att_s[lane * 4];
    float4 a2 = *(const float4*)&att_d[lane * 4];
    float ps = v.x * a1.x + v.y * a1.y + v.z * a1.z + v.w * a1.w;
    float pd = v.x * a2.x + v.y * a2.y + v.z * a2.z + v.w * a2.w;
#pragma unroll
    for (int o = 8; o >= 1; o >>= 1) {       // reduce within 16-lane halves (= heads)
        ps += __shfl_xor_sync(0xffffffffu, ps, o);
        pd += __shfl_xor_sync(0xffffffffu, pd, o);
    }
    if ((lane & 15) == 0) {
        int h = lane >> 4;
        g_asrc1[node * 2 + h] = ps;
        g_adst1[node * 2 + h] = pd;
    }
}

// ---------------- layer-1 fused softmax+aggregate (warp per dst) -------------
__global__ void k_edge1(const float* __restrict__ b1, int n) {
    int gt = blockIdx.x * blockDim.x + threadIdx.x;
    int d  = gt >> 5;
    if (d >= n) return;
    int lane = gt & 31;
    int beg = (int)g_off[d], end = (int)g_off[d + 1];
    float ad0 = g_adst1[d * 2 + 0];
    float ad1 = g_adst1[d * 2 + 1];
    int h = lane >> 4;
    float4 acc = make_float4(0.f, 0.f, 0.f, 0.f);
    float s0 = 0.f, s1 = 0.f;
    for (int base = beg; base < end; base += 32) {
        int myi = base + lane;
        float e0 = 0.f, e1 = 0.f;
        int msrc = 0;
        if (myi < end) {
            msrc = g_adj[myi];
            float2 as = *(const float2*)&g_asrc1[msrc * 2];
            e0 = __expf(lrelu(as.x + ad0));
            e1 = __expf(lrelu(as.y + ad1));
        }
        s0 += e0; s1 += e1;
        int cnt = min(32, end - base);
        for (int j = 0; j < cnt; j++) {
            int   src = __shfl_sync(0xffffffffu, msrc, j);
            float c0  = __shfl_sync(0xffffffffu, e0, j);
            float c1  = __shfl_sync(0xffffffffu, e1, j);
            float coef = h ? c1 : c0;
            float4 v = *(const float4*)&g_xw1[src * D1 + lane * 4];
            acc.x += v.x * coef; acc.y += v.y * coef;
            acc.z += v.z * coef; acc.w += v.w * coef;
        }
    }
#pragma unroll
    for (int o = 16; o >= 1; o >>= 1) {
        s0 += __shfl_xor_sync(0xffffffffu, s0, o);
        s1 += __shfl_xor_sync(0xffffffffu, s1, o);
    }
    float r = 1.f / ((h ? s1 : s0) + 1e-16f);
    float4 bb = *(const float4*)&b1[lane * 4];
    *(float4*)&g_out1[d * D1 + lane * 4] =
        make_float4(acc.x * r + bb.x, acc.y * r + bb.y, acc.z * r + bb.z, acc.w * r + bb.w);
}

// ---------------- layer-2 GEMM (relu fused on load) + att2 dots --------------
__global__ void k_gemm2(const float* __restrict__ att_s, const float* __restrict__ att_d, int n) {
    __shared__ float xs[8 * 132];
    int t  = threadIdx.x;            // 128 threads = 8 nodes x 16 outs
    int nb = blockIdx.x * 8;
#pragma unroll
    for (int i = 0; i < 8; i++) {
        int node = nb + i;
        float v = (node < n) ? g_out1[node * D1 + t] : 0.f;
        xs[i * 132 + t] = fmaxf(v, 0.f);     // relu
    }
    __syncthreads();
    int ni = t >> 4;
    int o  = t & 15;
    float a0 = 0.f, a1 = 0.f, a2 = 0.f, a3 = 0.f;
#pragma unroll
    for (int k4 = 0; k4 < D1 / 4; k4 += 4) {
#pragma unroll
        for (int u = 0; u < 4; u++) {
            float4 w  = g_w2t4[(k4 + u) * NC + o];
            float4 xv = *(const float4*)&xs[ni * 132 + (k4 + u) * 4];
            float p = xv.x * w.x + xv.y * w.y + xv.z * w.z + xv.w * w.w;
            if (u == 0) a0 += p; else if (u == 1) a1 += p; else if (u == 2) a2 += p; else a3 += p;
        }
    }
    float acc = (a0 + a1) + (a2 + a3);
    int node = nb + ni;
    if (node < n) g_xw2[node * NC + o] = acc;
    float ps = acc * att_s[o];
    float pd = acc * att_d[o];
#pragma unroll
    for (int j = 8; j >= 1; j >>= 1) {
        ps += __shfl_xor_sync(0xffffffffu, ps, j);
        pd += __shfl_xor_sync(0xffffffffu, pd, j);
    }
    if (o == 0 && node < n) { g_asrc2[node] = ps; g_adst2[node] = pd; }
}

// ---------------- layer-2 fused softmax+aggregate (warp per dst) -------------
__global__ void k_edge2(const float* __restrict__ b2, float* __restrict__ out, int n) {
    int gt = blockIdx.x * blockDim.x + threadIdx.x;
    int d  = gt >> 5;
    if (d >= n) return;
    int lane = gt & 31;
    int beg = (int)g_off[d], end = (int)g_off[d + 1];
    float add = g_adst2[d];
    int half = lane >> 4;
    int c    = lane & 15;
    float acc = 0.f, s = 0.f;
    for (int base = beg; base < end; base += 32) {
        int myi = base + lane;
        float ev = 0.f;
        int msrc = 0;
        if (myi < end) {
            msrc = g_adj[myi];
            ev = __expf(lrelu(g_asrc2[msrc] + add));
        }
        s += ev;
        int cnt = min(32, end - base);
        for (int j = 0; j < cnt; j += 2) {
            int jj = j + half;                  // lanes 0-15 edge j, 16-31 edge j+1
            int   src = __shfl_sync(0xffffffffu, msrc, jj & 31);
            float e   = __shfl_sync(0xffffffffu, ev, jj & 31);
            acc += g_xw2[src * NC + c] * e;
        }
    }
#pragma unroll
    for (int o = 16; o >= 1; o >>= 1)
        s += __shfl_xor_sync(0xffffffffu, s, o);
    acc += __shfl_xor_sync(0xffffffffu, acc, 16);
    if (half == 0) {
        float r = 1.f / (s + 1e-16f);
        out[d * NC + c] = acc * r + b2[c];
    }
}

// ---------------- launcher ----------------------------------------------------
extern "C" void kernel_launch(void* const* d_in, const int* in_sizes, int n_in,
                              void* d_out, int out_size) {
    const float* x   = (const float*)d_in[0];
    const int*   ei  = (const int*)d_in[1];      // int32
    const float* w1  = (const float*)d_in[2];
    const float* as1 = (const float*)d_in[3];
    const float* ad1 = (const float*)d_in[4];
    const float* b1  = (const float*)d_in[5];
    const float* w2  = (const float*)d_in[6];
    const float* as2 = (const float*)d_in[7];
    const float* ad2 = (const float*)d_in[8];
    const float* b2  = (const float*)d_in[9];
    float* out = (float*)d_out;

    int n  = in_sizes[0] / FIN;     // 50000
    int E  = in_sizes[1] / 2;       // 1600000
    int ET = E + n;                 // 1650000

    int prep_n = (FIN * D1 > n) ? FIN * D1 : n;
    k_prep<<<(prep_n + 255) / 256, 256>>>(w1, w2, n);

    // CSR by dst (shared by both layers)
    k_hist<<<(ET + 255) / 256, 256>>>(ei, E, ET);
    k_scan<<<1, 1024>>>(n);
    k_scatter<<<(ET + 255) / 256, 256>>>(ei, E, ET);

    // layer 1
    k_gemm1<<<(n + 31) / 32, 256>>>(x, n);
    k_att1<<<(n * 32 + 255) / 256, 256>>>(as1, ad1, n);
    k_edge1<<<(n * 32 + 255) / 256, 256>>>(b1, n);

    // layer 2
    k_gemm2<<<(n + 7) / 8, 128>>>(as2, ad2, n);
    k_edge2<<<(n * 32 + 255) / 256, 256>>>(b2, out, n);
}

// round 4
// speedup vs baseline: 2.5349x; 1.0628x over previous
#include <cuda_runtime.h>
#include <cuda_fp16.h>

// Problem constants (fixed shapes for this problem)
#define Nn    50000
#define FIN   128
#define D1    128           // H1*C1
#define H1    2
#define NC    16
#define EMAX  1600000
#define ETMAX (EMAX + Nn)

// ---------------- scratch (device globals; no allocation allowed) ------------
__device__ float4   g_w1t[128 * 32];        // [k][c4] -> w1[c4*4+cc][k]
__device__ float4   g_w2t4[(D1 / 4) * NC];  // [k4][o]
__device__ __half2  g_xw1h[Nn * 64];        // fp16 copy of xw1 (gather payload)
__device__ float    g_out1[Nn * D1];
__device__ float    g_asrc1[Nn * H1];
__device__ float    g_adst1[Nn * H1];
__device__ __half   g_xw2h[Nn * NC];        // fp16 copy of xw2 (gather payload)
__device__ float    g_asrc2[Nn];
__device__ float    g_adst2[Nn];
__device__ unsigned g_cnt[Nn];
__device__ unsigned g_off[Nn + 1];
__device__ unsigned g_cur[Nn];
__device__ int      g_adj[ETMAX];           // CSR by dst: src node ids

__device__ __forceinline__ float lrelu(float a) { return a > 0.f ? a : 0.2f * a; }

// ---------------- weight repack + counter zero -------------------------------
__global__ void k_prep(const float* __restrict__ w1, const float* __restrict__ w2, int n) {
    int i = blockIdx.x * blockDim.x + threadIdx.x;
    if (i < FIN * D1) {
        int c = i / FIN, k = i % FIN;             // w1: [D1][FIN] row-major
        ((float*)g_w1t)[(k * 32 + (c >> 2)) * 4 + (c & 3)] = w1[i];
    }
    if (i < NC * D1) {
        int o = i / D1, k = i % D1;               // w2: [NC][D1]
        ((float*)g_w2t4)[((k >> 2) * NC + o) * 4 + (k & 3)] = w2[i];
    }
    if (i < n) g_cnt[i] = 0u;
}

// ---------------- CSR build ---------------------------------------------------
__global__ void k_hist(const int* __restrict__ ei, int E, int ET) {
    int e = blockIdx.x * blockDim.x + threadIdx.x;
    if (e >= ET) return;
    int d = (e < E) ? ei[E + e] : (e - E);
    atomicAdd(&g_cnt[d], 1u);
}

__global__ void k_scan(int n) {
    __shared__ unsigned ssum[1024];
    int t = threadIdx.x;
    int chunk = (n + 1023) >> 10;
    int b = t * chunk;
    int e = min(b + chunk, n);
    unsigned sum = 0;
    for (int i = b; i < e; i++) sum += g_cnt[i];
    ssum[t] = sum;
    __syncthreads();
    for (int o = 1; o < 1024; o <<= 1) {
        unsigned v = (t >= o) ? ssum[t - o] : 0u;
        __syncthreads();
        ssum[t] += v;
        __syncthreads();
    }
    unsigned run = (t == 0) ? 0u : ssum[t - 1];
    for (int i = b; i < e; i++) {
        unsigned c = g_cnt[i];
        g_off[i] = run;
        g_cur[i] = run;
        run += c;
    }
    if (t == 0) g_off[n] = ssum[1023];
}

__global__ void k_scatter(const int* __restrict__ ei, int E, int ET) {
    int e = blockIdx.x * blockDim.x + threadIdx.x;
    if (e >= ET) return;
    int s, d;
    if (e < E) { s = ei[e]; d = ei[E + e]; } else { s = d = e - E; }
    unsigned pos = atomicAdd(&g_cur[d], 1u);
    g_adj[pos] = s;
}

// ------- layer-1 GEMM: xw1 = x @ w1^T (32 nodes/block) + att1 dots + fp16 ----
__global__ __launch_bounds__(256) void k_gemm1(const float* __restrict__ x,
                                               const float* __restrict__ att_s,
                                               const float* __restrict__ att_d, int n) {
    __shared__ float xs[128 * 33];
    int tid = threadIdx.x;
    int nb  = blockIdx.x * 32;
    for (int idx = tid; idx < 32 * 128; idx += 256) {
        int node = idx >> 7, k = idx & 127;
        xs[k * 33 + node] = (nb + node < n) ? x[(nb + node) * FIN + k] : 0.f;
    }
    __syncthreads();
    int c4 = tid & 31;     // channels c4*4 .. c4*4+3 (lane id)
    int ng = tid >> 5;     // nodes ng*4 .. ng*4+3 (warp id)
    float acc[4][4];
#pragma unroll
    for (int i = 0; i < 4; i++)
#pragma unroll
        for (int j = 0; j < 4; j++) acc[i][j] = 0.f;
#pragma unroll 8
    for (int k = 0; k < 128; k++) {
        float4 w = g_w1t[k * 32 + c4];
        float xv0 = xs[k * 33 + ng * 4 + 0];
        float xv1 = xs[k * 33 + ng * 4 + 1];
        float xv2 = xs[k * 33 + ng * 4 + 2];
        float xv3 = xs[k * 33 + ng * 4 + 3];
        acc[0][0] += xv0 * w.x; acc[0][1] += xv0 * w.y; acc[0][2] += xv0 * w.z; acc[0][3] += xv0 * w.w;
        acc[1][0] += xv1 * w.x; acc[1][1] += xv1 * w.y; acc[1][2] += xv1 * w.z; acc[1][3] += xv1 * w.w;
        acc[2][0] += xv2 * w.x; acc[2][1] += xv2 * w.y; acc[2][2] += xv2 * w.z; acc[2][3] += xv2 * w.w;
        acc[3][0] += xv3 * w.x; acc[3][1] += xv3 * w.y; acc[3][2] += xv3 * w.z; acc[3][3] += xv3 * w.w;
    }
    // store fp16 gather payload
#pragma unroll
    for (int i = 0; i < 4; i++) {
        int node = nb + ng * 4 + i;
        if (node < n) {
            g_xw1h[node * 64 + c4 * 2 + 0] = __floats2half2_rn(acc[i][0], acc[i][1]);
            g_xw1h[node * 64 + c4 * 2 + 1] = __floats2half2_rn(acc[i][2], acc[i][3]);
        }
    }
    // fused attention dots: reduce within 16-lane halves (= heads)
    float4 as4 = *(const float4*)&att_s[c4 * 4];
    float4 ad4 = *(const float4*)&att_d[c4 * 4];
#pragma unroll
    for (int i = 0; i < 4; i++) {
        float ps = acc[i][0] * as4.x + acc[i][1] * as4.y + acc[i][2] * as4.z + acc[i][3] * as4.w;
        float pd = acc[i][0] * ad4.x + acc[i][1] * ad4.y + acc[i][2] * ad4.z + acc[i][3] * ad4.w;
#pragma unroll
        for (int o = 8; o >= 1; o >>= 1) {
            ps += __shfl_xor_sync(0xffffffffu, ps, o);
            pd += __shfl_xor_sync(0xffffffffu, pd, o);
        }
        int node = nb + ng * 4 + i;
        if ((c4 & 15) == 0 && node < n) {
            int h = c4 >> 4;
            g_asrc1[node * 2 + h] = ps;
            g_adst1[node * 2 + h] = pd;
        }
    }
}

// ---------------- layer-1 fused softmax+aggregate (warp per dst) -------------
__global__ void k_edge1(const float* __restrict__ b1, int n) {
    int gt = blockIdx.x * blockDim.x + threadIdx.x;
    int d  = gt >> 5;
    if (d >= n) return;
    int lane = gt & 31;
    int beg = (int)g_off[d], end = (int)g_off[d + 1];
    float ad0 = g_adst1[d * 2 + 0];
    float ad1 = g_adst1[d * 2 + 1];
    int h = lane >> 4;
    float4 acc = make_float4(0.f, 0.f, 0.f, 0.f);
    float s0 = 0.f, s1 = 0.f;
    for (int base = beg; base < end; base += 32) {
        int myi = base + lane;
        float e0 = 0.f, e1 = 0.f;
        int msrc = 0;
        if (myi < end) {
            msrc = g_adj[myi];
            float2 as = *(const float2*)&g_asrc1[msrc * 2];
            e0 = __expf(lrelu(as.x + ad0));
            e1 = __expf(lrelu(as.y + ad1));
        }
        s0 += e0; s1 += e1;
        int cnt = min(32, end - base);
#pragma unroll 4
        for (int j = 0; j < cnt; j++) {
            int   src = __shfl_sync(0xffffffffu, msrc, j);
            float c0  = __shfl_sync(0xffffffffu, e0, j);
            float c1  = __shfl_sync(0xffffffffu, e1, j);
            float coef = h ? c1 : c0;
            uint2 p = *(const uint2*)&g_xw1h[src * 64 + lane * 2];
            float2 v01 = __half22float2(*(__half2*)&p.x);
            float2 v23 = __half22float2(*(__half2*)&p.y);
            acc.x += v01.x * coef; acc.y += v01.y * coef;
            acc.z += v23.x * coef; acc.w += v23.y * coef;
        }
    }
#pragma unroll
    for (int o = 16; o >= 1; o >>= 1) {
        s0 += __shfl_xor_sync(0xffffffffu, s0, o);
        s1 += __shfl_xor_sync(0xffffffffu, s1, o);
    }
    float r = 1.f / ((h ? s1 : s0) + 1e-16f);
    float4 bb = *(const float4*)&b1[lane * 4];
    *(float4*)&g_out1[d * D1 + lane * 4] =
        make_float4(acc.x * r + bb.x, acc.y * r + bb.y, acc.z * r + bb.z, acc.w * r + bb.w);
}

// ---------------- layer-2 GEMM (relu fused on load) + att2 dots --------------
__global__ void k_gemm2(const float* __restrict__ att_s, const float* __restrict__ att_d, int n) {
    __shared__ float xs[8 * 132];
    int t  = threadIdx.x;            // 128 threads = 8 nodes x 16 outs
    int nb = blockIdx.x * 8;
#pragma unroll
    for (int i = 0; i < 8; i++) {
        int node = nb + i;
        float v = (node < n) ? g_out1[node * D1 + t] : 0.f;
        xs[i * 132 + t] = fmaxf(v, 0.f);     // relu
    }
    __syncthreads();
    int ni = t >> 4;
    int o  = t & 15;
    float a0 = 0.f, a1 = 0.f, a2 = 0.f, a3 = 0.f;
#pragma unroll
    for (int k4 = 0; k4 < D1 / 4; k4 += 4) {
#pragma unroll
        for (int u = 0; u < 4; u++) {
            float4 w  = g_w2t4[(k4 + u) * NC + o];
            float4 xv = *(const float4*)&xs[ni * 132 + (k4 + u) * 4];
            float p = xv.x * w.x + xv.y * w.y + xv.z * w.z + xv.w * w.w;
            if (u == 0) a0 += p; else if (u == 1) a1 += p; else if (u == 2) a2 += p; else a3 += p;
        }
    }
    float acc = (a0 + a1) + (a2 + a3);
    int node = nb + ni;
    if (node < n) g_xw2h[node * NC + o] = __float2half(acc);
    float ps = acc * att_s[o];
    float pd = acc * att_d[o];
#pragma unroll
    for (int j = 8; j >= 1; j >>= 1) {
        ps += __shfl_xor_sync(0xffffffffu, ps, j);
        pd += __shfl_xor_sync(0xffffffffu, pd, j);
    }
    if (o == 0 && node < n) { g_asrc2[node] = ps; g_adst2[node] = pd; }
}

// ---------------- layer-2 fused softmax+aggregate (warp per dst) -------------
__global__ void k_edge2(const float* __restrict__ b2, float* __restrict__ out, int n) {
    int gt = blockIdx.x * blockDim.x + threadIdx.x;
    int d  = gt >> 5;
    if (d >= n) return;
    int lane = gt & 31;
    int beg = (int)g_off[d], end = (int)g_off[d + 1];
    float add = g_adst2[d];
    int half = lane >> 4;
    int c    = lane & 15;
    float acc = 0.f, s = 0.f;
    for (int base = beg; base < end; base += 32) {
        int myi = base + lane;
        float ev = 0.f;
        int msrc = 0;
        if (myi < end) {
            msrc = g_adj[myi];
            ev = __expf(lrelu(g_asrc2[msrc] + add));
        }
        s += ev;
        int cnt = min(32, end - base);
#pragma unroll 4
        for (int j = 0; j < cnt; j += 2) {
            int jj = j + half;                  // lanes 0-15 edge j, 16-31 edge j+1
            int   src = __shfl_sync(0xffffffffu, msrc, jj & 31);
            float e   = __shfl_sync(0xffffffffu, ev, jj & 31);
            if (jj < cnt)
                acc += __half2float(g_xw2h[src * NC + c]) * e;
        }
    }
#pragma unroll
    for (int o = 16; o >= 1; o >>= 1)
        s += __shfl_xor_sync(0xffffffffu, s, o);
    acc += __shfl_xor_sync(0xffffffffu, acc, 16);
    if (half == 0) {
        float r = 1.f / (s + 1e-16f);
        out[d * NC + c] = acc * r + b2[c];
    }
}

// ---------------- launcher ----------------------------------------------------
extern "C" void kernel_launch(void* const* d_in, const int* in_sizes, int n_in,
                              void* d_out, int out_size) {
    const float* x   = (const float*)d_in[0];
    const int*   ei  = (const int*)d_in[1];      // int32
    const float* w1  = (const float*)d_in[2];
    const float* as1 = (const float*)d_in[3];
    const float* ad1 = (const float*)d_in[4];
    const float* b1  = (const float*)d_in[5];
    const float* w2  = (const float*)d_in[6];
    const float* as2 = (const float*)d_in[7];
    const float* ad2 = (const float*)d_in[8];
    const float* b2  = (const float*)d_in[9];
    float* out = (float*)d_out;

    int n  = in_sizes[0] / FIN;     // 50000
    int E  = in_sizes[1] / 2;       // 1600000
    int ET = E + n;                 // 1650000

    int prep_n = (FIN * D1 > n) ? FIN * D1 : n;
    k_prep<<<(prep_n + 255) / 256, 256>>>(w1, w2, n);

    // CSR by dst (shared by both layers)
    k_hist<<<(ET + 255) / 256, 256>>>(ei, E, ET);
    k_scan<<<1, 1024>>>(n);
    k_scatter<<<(ET + 255) / 256, 256>>>(ei, E, ET);

    // layer 1 (att1 dots + fp16 payload fused into gemm1)
    k_gemm1<<<(n + 31) / 32, 256>>>(x, as1, ad1, n);
    k_edge1<<<(n * 32 + 255) / 256, 256>>>(b1, n);

    // layer 2
    k_gemm2<<<(n + 7) / 8, 128>>>(as2, ad2, n);
    k_edge2<<<(n * 32 + 255) / 256, 256>>>(b2, out, n);
}

// round 5
// speedup vs baseline: 2.5492x; 1.0056x over previous
#include <cuda_runtime.h>
#include <cuda_fp16.h>

// Problem constants (fixed shapes for this problem)
#define Nn    50000
#define FIN   128
#define D1    128           // H1*C1
#define H1    2
#define NC    16
#define EMAX  1600000
#define ETMAX (EMAX + Nn)

// ---------------- scratch (device globals; no allocation allowed) ------------
__device__ float4   g_w1t[128 * 32];        // [k][c4] -> w1[c4*4+cc][k]
__device__ float4   g_w2t4[(D1 / 4) * NC];  // [k4][o]
__device__ __half2  g_xw1h[Nn * 64];        // fp16 copy of xw1 (gather payload)
__device__ float    g_out1[Nn * D1];
__device__ float    g_asrc1[Nn * H1];
__device__ float    g_adst1[Nn * H1];
__device__ __half   g_xw2h[Nn * NC];        // fp16 copy of xw2 (gather payload)
__device__ float    g_asrc2[Nn];
__device__ float    g_adst2[Nn];
__device__ unsigned g_cnt[Nn];
__device__ unsigned g_off[Nn + 1];
__device__ unsigned g_cur[Nn];
__device__ int      g_adj[ETMAX];           // CSR by dst: src node ids

__device__ __forceinline__ float lrelu(float a) { return a > 0.f ? a : 0.2f * a; }

// ---------------- weight repack + counter zero -------------------------------
__global__ void k_prep(const float* __restrict__ w1, const float* __restrict__ w2, int n) {
    int i = blockIdx.x * blockDim.x + threadIdx.x;
    if (i < FIN * D1) {
        int c = i / FIN, k = i % FIN;             // w1: [D1][FIN] row-major
        ((float*)g_w1t)[(k * 32 + (c >> 2)) * 4 + (c & 3)] = w1[i];
    }
    if (i < NC * D1) {
        int o = i / D1, k = i % D1;               // w2: [NC][D1]
        ((float*)g_w2t4)[((k >> 2) * NC + o) * 4 + (k & 3)] = w2[i];
    }
    if (i < n) g_cnt[i] = 0u;
}

// ---------------- CSR build ---------------------------------------------------
__global__ void k_hist(const int* __restrict__ ei, int E, int ET) {
    int e = blockIdx.x * blockDim.x + threadIdx.x;
    if (e >= ET) return;
    int d = (e < E) ? ei[E + e] : (e - E);
    atomicAdd(&g_cnt[d], 1u);
}

__global__ void k_scan(int n) {
    __shared__ unsigned ssum[1024];
    int t = threadIdx.x;
    int chunk = (n + 1023) >> 10;
    int b = t * chunk;
    int e = min(b + chunk, n);
    unsigned sum = 0;
    for (int i = b; i < e; i++) sum += g_cnt[i];
    ssum[t] = sum;
    __syncthreads();
    for (int o = 1; o < 1024; o <<= 1) {
        unsigned v = (t >= o) ? ssum[t - o] : 0u;
        __syncthreads();
        ssum[t] += v;
        __syncthreads();
    }
    unsigned run = (t == 0) ? 0u : ssum[t - 1];
    for (int i = b; i < e; i++) {
        unsigned c = g_cnt[i];
        g_off[i] = run;
        g_cur[i] = run;
        run += c;
    }
    if (t == 0) g_off[n] = ssum[1023];
}

__global__ void k_scatter(const int* __restrict__ ei, int E, int ET) {
    int e = blockIdx.x * blockDim.x + threadIdx.x;
    if (e >= ET) return;
    int s, d;
    if (e < E) { s = ei[e]; d = ei[E + e]; } else { s = d = e - E; }
    unsigned pos = atomicAdd(&g_cur[d], 1u);
    g_adj[pos] = s;
}

// ------- layer-1 GEMM: xw1 = x @ w1^T (32 nodes/block) + att1 dots + fp16 ----
__global__ __launch_bounds__(256) void k_gemm1(const float* __restrict__ x,
                                               const float* __restrict__ att_s,
                                               const float* __restrict__ att_d, int n) {
    __shared__ float xs[128 * 33];
    int tid = threadIdx.x;
    int nb  = blockIdx.x * 32;
    for (int idx = tid; idx < 32 * 128; idx += 256) {
        int node = idx >> 7, k = idx & 127;
        xs[k * 33 + node] = (nb + node < n) ? x[(nb + node) * FIN + k] : 0.f;
    }
    __syncthreads();
    int c4 = tid & 31;     // channels c4*4 .. c4*4+3 (lane id)
    int ng = tid >> 5;     // nodes ng*4 .. ng*4+3 (warp id)
    float acc[4][4];
#pragma unroll
    for (int i = 0; i < 4; i++)
#pragma unroll
        for (int j = 0; j < 4; j++) acc[i][j] = 0.f;
#pragma unroll 8
    for (int k = 0; k < 128; k++) {
        float4 w = g_w1t[k * 32 + c4];
        float xv0 = xs[k * 33 + ng * 4 + 0];
        float xv1 = xs[k * 33 + ng * 4 + 1];
        float xv2 = xs[k * 33 + ng * 4 + 2];
        float xv3 = xs[k * 33 + ng * 4 + 3];
        acc[0][0] += xv0 * w.x; acc[0][1] += xv0 * w.y; acc[0][2] += xv0 * w.z; acc[0][3] += xv0 * w.w;
        acc[1][0] += xv1 * w.x; acc[1][1] += xv1 * w.y; acc[1][2] += xv1 * w.z; acc[1][3] += xv1 * w.w;
        acc[2][0] += xv2 * w.x; acc[2][1] += xv2 * w.y; acc[2][2] += xv2 * w.z; acc[2][3] += xv2 * w.w;
        acc[3][0] += xv3 * w.x; acc[3][1] += xv3 * w.y; acc[3][2] += xv3 * w.z; acc[3][3] += xv3 * w.w;
    }
    // store fp16 gather payload
#pragma unroll
    for (int i = 0; i < 4; i++) {
        int node = nb + ng * 4 + i;
        if (node < n) {
            g_xw1h[node * 64 + c4 * 2 + 0] = __floats2half2_rn(acc[i][0], acc[i][1]);
            g_xw1h[node * 64 + c4 * 2 + 1] = __floats2half2_rn(acc[i][2], acc[i][3]);
        }
    }
    // fused attention dots: reduce within 16-lane halves (= heads)
    float4 as4 = *(const float4*)&att_s[c4 * 4];
    float4 ad4 = *(const float4*)&att_d[c4 * 4];
#pragma unroll
    for (int i = 0; i < 4; i++) {
        float ps = acc[i][0] * as4.x + acc[i][1] * as4.y + acc[i][2] * as4.z + acc[i][3] * as4.w;
        float pd = acc[i][0] * ad4.x + acc[i][1] * ad4.y + acc[i][2] * ad4.z + acc[i][3] * ad4.w;
#pragma unroll
        for (int o = 8; o >= 1; o >>= 1) {
            ps += __shfl_xor_sync(0xffffffffu, ps, o);
            pd += __shfl_xor_sync(0xffffffffu, pd, o);
        }
        int node = nb + ng * 4 + i;
        if ((c4 & 15) == 0 && node < n) {
            int h = c4 >> 4;
            g_asrc1[node * 2 + h] = ps;
            g_adst1[node * 2 + h] = pd;
        }
    }
}

// ---------------- layer-1 fused softmax+aggregate (warp per dst) -------------
__global__ void k_edge1(const float* __restrict__ b1, int n) {
    int gt = blockIdx.x * blockDim.x + threadIdx.x;
    int d  = gt >> 5;
    if (d >= n) return;
    int lane = gt & 31;
    int beg = (int)g_off[d], end = (int)g_off[d + 1];
    float ad0 = g_adst1[d * 2 + 0];
    float ad1 = g_adst1[d * 2 + 1];
    int h = lane >> 4;
    float4 acc = make_float4(0.f, 0.f, 0.f, 0.f);
    float s0 = 0.f, s1 = 0.f;
    for (int base = beg; base < end; base += 32) {
        int myi = base + lane;
        float e0 = 0.f, e1 = 0.f;
        int msrc = 0;
        if (myi < end) {
            msrc = g_adj[myi];
            float2 as = *(const float2*)&g_asrc1[msrc * 2];
            e0 = __expf(lrelu(as.x + ad0));
            e1 = __expf(lrelu(as.y + ad1));
        }
        s0 += e0; s1 += e1;
        int cnt = min(32, end - base);
#pragma unroll 4
        for (int j = 0; j < cnt; j++) {
            int   src = __shfl_sync(0xffffffffu, msrc, j);
            float c0  = __shfl_sync(0xffffffffu, e0, j);
            float c1  = __shfl_sync(0xffffffffu, e1, j);
            float coef = h ? c1 : c0;
            uint2 p = *(const uint2*)&g_xw1h[src * 64 + lane * 2];
            float2 v01 = __half22float2(*(__half2*)&p.x);
            float2 v23 = __half22float2(*(__half2*)&p.y);
            acc.x += v01.x * coef; acc.y += v01.y * coef;
            acc.z += v23.x * coef; acc.w += v23.y * coef;
        }
    }
#pragma unroll
    for (int o = 16; o >= 1; o >>= 1) {
        s0 += __shfl_xor_sync(0xffffffffu, s0, o);
        s1 += __shfl_xor_sync(0xffffffffu, s1, o);
    }
    float r = 1.f / ((h ? s1 : s0) + 1e-16f);
    float4 bb = *(const float4*)&b1[lane * 4];
    *(float4*)&g_out1[d * D1 + lane * 4] =
        make_float4(acc.x * r + bb.x, acc.y * r + bb.y, acc.z * r + bb.z, acc.w * r + bb.w);
}

// ---------------- layer-2 GEMM (relu fused on load) + att2 dots --------------
__global__ void k_gemm2(const float* __restrict__ att_s, const float* __restrict__ att_d, int n) {
    __shared__ float xs[8 * 132];
    int t  = threadIdx.x;            // 128 threads = 8 nodes x 16 outs
    int nb = blockIdx.x * 8;
#pragma unroll
    for (int i = 0; i < 8; i++) {
        int node = nb + i;
        float v = (node < n) ? g_out1[node * D1 + t] : 0.f;
        xs[i * 132 + t] = fmaxf(v, 0.f);     // relu
    }
    __syncthreads();
    int ni = t >> 4;
    int o  = t & 15;
    float a0 = 0.f, a1 = 0.f, a2 = 0.f, a3 = 0.f;
#pragma unroll
    for (int k4 = 0; k4 < D1 / 4; k4 += 4) {
#pragma unroll
        for (int u = 0; u < 4; u++) {
            float4 w  = g_w2t4[(k4 + u) * NC + o];
            float4 xv = *(const float4*)&xs[ni * 132 + (k4 + u) * 4];
            float p = xv.x * w.x + xv.y * w.y + xv.z * w.z + xv.w * w.w;
            if (u == 0) a0 += p; else if (u == 1) a1 += p; else if (u == 2) a2 += p; else a3 += p;
        }
    }
    float acc = (a0 + a1) + (a2 + a3);
    int node = nb + ni;
    if (node < n) g_xw2h[node * NC + o] = __float2half(acc);
    float ps = acc * att_s[o];
    float pd = acc * att_d[o];
#pragma unroll
    for (int j = 8; j >= 1; j >>= 1) {
        ps += __shfl_xor_sync(0xffffffffu, ps, j);
        pd += __shfl_xor_sync(0xffffffffu, pd, j);
    }
    if (o == 0 && node < n) { g_asrc2[node] = ps; g_adst2[node] = pd; }
}

// ---------------- layer-2 fused softmax+aggregate (warp per dst) -------------
__global__ void k_edge2(const float* __restrict__ b2, float* __restrict__ out, int n) {
    int gt = blockIdx.x * blockDim.x + threadIdx.x;
    int d  = gt >> 5;
    if (d >= n) return;
    int lane = gt & 31;
    int beg = (int)g_off[d], end = (int)g_off[d + 1];
    float add = g_adst2[d];
    int half = lane >> 4;
    int c    = lane & 15;
    float acc = 0.f, s = 0.f;
    for (int base = beg; base < end; base += 32) {
        int myi = base + lane;
        float ev = 0.f;
        int msrc = 0;
        if (myi < end) {
            msrc = g_adj[myi];
            ev = __expf(lrelu(g_asrc2[msrc] + add));
        }
        s += ev;
        int cnt = min(32, end - base);
#pragma unroll 4
        for (int j = 0; j < cnt; j += 2) {
            int jj = j + half;                  // lanes 0-15 edge j, 16-31 edge j+1
            int   src = __shfl_sync(0xffffffffu, msrc, jj & 31);
            float e   = __shfl_sync(0xffffffffu, ev, jj & 31);
            if (jj < cnt)
                acc += __half2float(g_xw2h[src * NC + c]) * e;
        }
    }
#pragma unroll
    for (int o = 16; o >= 1; o >>= 1)
        s += __shfl_xor_sync(0xffffffffu, s, o);
    acc += __shfl_xor_sync(0xffffffffu, acc, 16);
    if (half == 0) {
        float r = 1.f / (s + 1e-16f);
        out[d * NC + c] = acc * r + b2[c];
    }
}

// ---------------- launcher ----------------------------------------------------
extern "C" void kernel_launch(void* const* d_in, const int* in_sizes, int n_in,
                              void* d_out, int out_size) {
    const float* x   = (const float*)d_in[0];
    const int*   ei  = (const int*)d_in[1];      // int32
    const float* w1  = (const float*)d_in[2];
    const float* as1 = (const float*)d_in[3];
    const float* ad1 = (const float*)d_in[4];
    const float* b1  = (const float*)d_in[5];
    const float* w2  = (const float*)d_in[6];
    const float* as2 = (const float*)d_in[7];
    const float* ad2 = (const float*)d_in[8];
    const float* b2  = (const float*)d_in[9];
    float* out = (float*)d_out;

    int n  = in_sizes[0] / FIN;     // 50000
    int E  = in_sizes[1] / 2;       // 1600000
    int ET = E + n;                 // 1650000

    int prep_n = (FIN * D1 > n) ? FIN * D1 : n;
    k_prep<<<(prep_n + 255) / 256, 256>>>(w1, w2, n);

    // CSR by dst (shared by both layers)
    k_hist<<<(ET + 255) / 256, 256>>>(ei, E, ET);
    k_scan<<<1, 1024>>>(n);
    k_scatter<<<(ET + 255) / 256, 256>>>(ei, E, ET);

    // layer 1 (att1 dots + fp16 payload fused into gemm1)
    k_gemm1<<<(n + 31) / 32, 256>>>(x, as1, ad1, n);
    k_edge1<<<(n * 32 + 255) / 256, 256>>>(b1, n);

    // layer 2
    k_gemm2<<<(n + 7) / 8, 128>>>(as2, ad2, n);
    k_edge2<<<(n * 32 + 255) / 256, 256>>>(b2, out, n);
}